// round 7
// baseline (speedup 1.0000x reference)
#include <cuda_runtime.h>
#include <cstdint>

// Fixed problem: x [256,2048,7,7] fp32, x0 [256,49,1] fp32, out scalar fp32
#define BATCH   256
#define NQ      4                    // K-split partials per batch
#define NCTA    (BATCH * NQ)         // 1024
#define KQ      512                  // channels per CTA
#define KCH     32                   // channels per smem chunk
#define NCH     (KQ / KCH)           // 16
#define NDIM    49
#define SROW    72                   // floats/row: bank = (8k+n)%32 -> conflict-free frags
#define BUFF    (KCH * SROW)         // 2304 floats per buffer
#define THREADS 128
#define EPSV    1e-12f

__device__ float g_partial[NCTA][NDIM * NDIM];   // ~9.8 MB scratch
__device__ float g_penalty[BATCH];
__device__ int   g_cnt[BATCH];                   // zero-init; reset each run
__device__ int   g_cnt_all;

static __device__ __forceinline__ uint32_t f2tf32(float f) {
    uint32_t r;
    asm("cvt.rna.tf32.f32 %0, %1;" : "=r"(r) : "f"(f));
    return r;
}

// m16n8k8 tf32 (sm_80 PTX, valid on base sm_103). Standard fragment layouts.
static __device__ __forceinline__ void mma8(float* c,
    uint32_t a0, uint32_t a1, uint32_t a2, uint32_t a3,
    uint32_t b0, uint32_t b1)
{
    asm("mma.sync.aligned.m16n8k8.row.col.f32.tf32.tf32.f32 "
        "{%0,%1,%2,%3}, {%4,%5,%6,%7}, {%8,%9}, {%0,%1,%2,%3};"
        : "+f"(c[0]), "+f"(c[1]), "+f"(c[2]), "+f"(c[3])
        : "r"(a0), "r"(a1), "r"(a2), "r"(a3), "r"(b0), "r"(b1));
}

// Block-wide sum over first 49 lanes' values (all 128 threads call).
static __device__ __forceinline__ float reduce49(float v, int t, float* sarr) {
    if (t < 64) sarr[t] = (t < NDIM) ? v : 0.0f;
    __syncthreads();
    if (t < 32) {
        float r = sarr[t] + sarr[t + 32];
        r += __shfl_xor_sync(0xffffffffu, r, 16);
        r += __shfl_xor_sync(0xffffffffu, r, 8);
        r += __shfl_xor_sync(0xffffffffu, r, 4);
        r += __shfl_xor_sync(0xffffffffu, r, 2);
        r += __shfl_xor_sync(0xffffffffu, r, 1);
        if (t == 0) sarr[0] = r;
    }
    __syncthreads();
    float out = sarr[0];
    __syncthreads();
    return out;
}

// store a 32x49 chunk (held as 4 float4/thread; tail: t<8 for i=3) into [k][n] tf32 layout
static __device__ __forceinline__ void store_chunk(float* dst, const float4* pre, int t) {
#pragma unroll
    for (int i = 0; i < 4; i++) {
        if (i < 3 || t < 8) {
            const int flat = (t + i * THREADS) * 4;
            float v[4] = {pre[i].x, pre[i].y, pre[i].z, pre[i].w};
#pragma unroll
            for (int e = 0; e < 4; e++) {
                const int f = flat + e;
                const int c = f / NDIM;
                const int n = f - c * NDIM;
                dst[c * SROW + n] = __uint_as_float(f2tf32(v[e]));
            }
        }
    }
}

__global__ void __launch_bounds__(THREADS, 6)
ofp_fused(const float* __restrict__ x, const float* __restrict__ x0,
          float* __restrict__ out)
{
    __shared__ float smem[2 * BUFF];          // 18432 B static
    float* sA    = smem;                      // [2401] aliases buffers (dead by PI time)
    float* sx    = smem + 2432;
    float* sred  = smem + 2496;
    int*   scomm = (int*)(smem + 2560);
    float* sfin  = smem + 2624;               // [128] final tree staging

    const int t    = threadIdx.x;
    const int lane = t & 31, wid = t >> 5;
    const int l4   = lane & 3, ld4 = lane >> 2;
    const int cta  = blockIdx.x;
    const int b    = cta >> 2, q = cta & 3;
    const int qm   = wid >> 1, qn = wid & 1;  // warp's 32x32 quadrant
    const int m0   = qm * 32 + ld4;
    const int n0   = qn * 32 + ld4;

    const float* __restrict__ xq =
        x + (size_t)b * (2048 * NDIM) + (size_t)q * (KQ * NDIM);

    // zero pad columns n in [49,64) of both buffers (read by frags, never refilled)
    for (int i = t; i < 2 * KCH * 15; i += THREADS) {
        const int bi  = i / (KCH * 15);
        const int rem = i - bi * (KCH * 15);
        const int r   = rem / 15;
        const int n   = 49 + rem - r * 15;
        smem[bi * BUFF + r * SROW + n] = 0.0f;
    }

    float acc[2][4][4];
#pragma unroll
    for (int mt = 0; mt < 2; mt++)
#pragma unroll
        for (int nt = 0; nt < 4; nt++)
#pragma unroll
            for (int ci = 0; ci < 4; ci++) acc[mt][nt][ci] = 0.0f;

    // ---- prologue: chunk 0 -> buf0 ----
    float4 pre[4];
    {
        const float4* __restrict__ s0 = (const float4*)xq;
#pragma unroll
        for (int i = 0; i < 4; i++)
            if (i < 3 || t < 8) pre[i] = __ldg(s0 + t + i * THREADS);
        store_chunk(smem, pre, t);
    }
    __syncthreads();

    // ---- main loop: 16 chunks, double-buffered, 1 sync/iter ----
    for (int ch = 0; ch < NCH; ch++) {
        if (ch + 1 < NCH) {
            const float4* __restrict__ s1 =
                (const float4*)(xq + (size_t)(ch + 1) * (KCH * NDIM));
#pragma unroll
            for (int i = 0; i < 4; i++)
                if (i < 3 || t < 8) pre[i] = __ldg(s1 + t + i * THREADS);
        }
        const float* bc = smem + (ch & 1) * BUFF;
#pragma unroll
        for (int kb = 0; kb < 4; kb++) {
            const float* lo = bc + (kb * 8 + l4) * SROW;
            const float* hi = lo + 4 * SROW;
            uint32_t b0[4], b1[4];
#pragma unroll
            for (int nt = 0; nt < 4; nt++) {
                b0[nt] = __float_as_uint(lo[n0 + nt * 8]);
                b1[nt] = __float_as_uint(hi[n0 + nt * 8]);
            }
#pragma unroll
            for (int mt = 0; mt < 2; mt++) {
                const uint32_t a0 = __float_as_uint(lo[m0 + mt * 16]);
                const uint32_t a1 = __float_as_uint(lo[m0 + mt * 16 + 8]);
                const uint32_t a2 = __float_as_uint(hi[m0 + mt * 16]);
                const uint32_t a3 = __float_as_uint(hi[m0 + mt * 16 + 8]);
#pragma unroll
                for (int nt = 0; nt < 4; nt++)
                    mma8(acc[mt][nt], a0, a1, a2, a3, b0[nt], b1[nt]);
            }
        }
        if (ch + 1 < NCH) store_chunk(smem + ((ch + 1) & 1) * BUFF, pre, t);
        __syncthreads();
    }

    // ---- write 49x49 partial Gram ----
    {
        float* __restrict__ gp = g_partial[cta];
#pragma unroll
        for (int mt = 0; mt < 2; mt++)
#pragma unroll
            for (int nt = 0; nt < 4; nt++) {
                const int r0 = qm * 32 + mt * 16 + ld4;
                const int c0 = qn * 32 + nt * 8 + 2 * l4;
                const float* a = acc[mt][nt];
                if (r0 < NDIM) {
                    if (c0 < NDIM)     gp[r0 * NDIM + c0]     = a[0];
                    if (c0 + 1 < NDIM) gp[r0 * NDIM + c0 + 1] = a[1];
                }
                if (r0 + 8 < NDIM) {
                    if (c0 < NDIM)     gp[(r0 + 8) * NDIM + c0]     = a[2];
                    if (c0 + 1 < NDIM) gp[(r0 + 8) * NDIM + c0 + 1] = a[3];
                }
            }
    }
    __syncthreads();
    __threadfence();
    if (t == 0) scomm[0] = atomicAdd(&g_cnt[b], 1);
    __syncthreads();
    if (scomm[0] != NQ - 1) return;          // not the last partial of this batch

    // ================= last arriver: power iteration for batch b =================
    __threadfence();
    {
        const float* __restrict__ p0 = g_partial[(b << 2) + 0];
        const float* __restrict__ p1 = g_partial[(b << 2) + 1];
        const float* __restrict__ p2 = g_partial[(b << 2) + 2];
        const float* __restrict__ p3 = g_partial[(b << 2) + 3];
        for (int i = t; i < NDIM * NDIM; i += THREADS)
            sA[i] = (__ldcg(p0 + i) + __ldcg(p1 + i)) +
                    (__ldcg(p2 + i) + __ldcg(p3 + i));
    }
    if (t < NDIM) sx[t] = x0[b * NDIM + t];
    __syncthreads();

    // PI-1: largest eigenvalue of ATA
    for (int it = 0; it < 9; it++) {
        float y = 0.0f;
        if (t < NDIM) {
            const float* __restrict__ rA = &sA[t * NDIM];
#pragma unroll
            for (int m = 0; m < NDIM; m++) y = fmaf(rA[m], sx[m], y);
        }
        const float n2  = reduce49(y * y, t, sred);
        const float nrm = fmaxf(sqrtf(n2), EPSV);
        if (t < NDIM) sx[t] = y / nrm;
        __syncthreads();
    }
    float y = 0.0f, xv = 0.0f;
    if (t < NDIM) {
        xv = sx[t];
        const float* __restrict__ rA = &sA[t * NDIM];
#pragma unroll
        for (int m = 0; m < NDIM; m++) y = fmaf(rA[m], sx[m], y);
    }
    float num = reduce49(y * xv, t, sred);
    float den = reduce49(xv * xv, t, sred);
    const float largest = num / den;

    // PI-2 on (ATA - largest*I), warm-started from x1
    for (int it = 0; it < 9; it++) {
        float ys = 0.0f;
        if (t < NDIM) {
            const float* __restrict__ rA = &sA[t * NDIM];
#pragma unroll
            for (int m = 0; m < NDIM; m++) ys = fmaf(rA[m], sx[m], ys);
            ys -= largest * sx[t];
        }
        const float n2  = reduce49(ys * ys, t, sred);
        const float nrm = fmaxf(sqrtf(n2), EPSV);
        if (t < NDIM) sx[t] = ys / nrm;
        __syncthreads();
    }
    y = 0.0f; xv = 0.0f;
    if (t < NDIM) {
        xv = sx[t];
        const float* __restrict__ rA = &sA[t * NDIM];
#pragma unroll
        for (int m = 0; m < NDIM; m++) y = fmaf(rA[m], sx[m], y);
        y -= largest * xv;
    }
    num = reduce49(y * xv, t, sred);
    den = reduce49(xv * xv, t, sred);
    const float smallest = (num / den) + largest;

    if (t == 0) {
        const float r = largest / smallest - 1.0f;
        g_penalty[b] = r * r;                 // BETA = 1
    }
    __threadfence();
    if (t == 0) scomm[0] = atomicAdd(&g_cnt_all, 1);
    __syncthreads();
    if (scomm[0] != BATCH - 1) return;        // not the global last batch

    // ================= global last arriver: deterministic finalize =================
    __threadfence();
    sfin[t] = __ldcg(&g_penalty[t]) + __ldcg(&g_penalty[t + 128]);
    __syncthreads();
#pragma unroll
    for (int off = 64; off > 0; off >>= 1) {
        if (t < off) sfin[t] += sfin[t + off];
        __syncthreads();
    }
    if (t == 0) out[0] = sfin[0] * (1.0f / (float)BATCH);

    // reset counters for the next graph replay
    g_cnt[t] = 0;
    g_cnt[t + 128] = 0;
    if (t == 0) g_cnt_all = 0;
}

extern "C" void kernel_launch(void* const* d_in, const int* in_sizes, int n_in,
                              void* d_out, int out_size) {
    const float* x  = (const float*)d_in[0];   // [256, 2048, 7, 7]
    const float* x0 = (const float*)d_in[1];   // [256, 49, 1]
    float* out = (float*)d_out;

    ofp_fused<<<NCTA, THREADS>>>(x, x0, out);
}

// round 8
// speedup vs baseline: 1.0829x; 1.0829x over previous
#include <cuda_runtime.h>
#include <cstdint>

// Fixed problem: x [256,2048,7,7] fp32, x0 [256,49,1] fp32, out scalar fp32
#define BATCH   256
#define NQ      4                     // K-split partials per batch
#define NCTA    (BATCH * NQ)          // 1024
#define KQ      512                   // channels per CTA
#define KCH     64                    // channels per chunk
#define NCH     (KQ / KCH)            // 8
#define NDIM    49
#define PAIRS   32                    // KCH/2 packed k-pair rows per chunk
#define SROW    72                    // f16x2 words per row -> conflict-free frags
#define BUFW    (PAIRS * SROW)        // 2304 words per buffer
#define WCHUNK  (PAIRS * NDIM)        // 1568 packed words per chunk = 12*128 + 32
#define THREADS 128
#define EPSV    1e-12f

__device__ float g_partial[NCTA][NDIM * NDIM];
__device__ float g_penalty[BATCH];
__device__ int   g_cnt[BATCH];        // zero-init; reset each run
__device__ int   g_cnt_all;

// pack two fp32 channel values into f16x2 (hi = k odd, lo = k even)
static __device__ __forceinline__ uint32_t pack_h2(float k_odd, float k_even) {
    uint32_t d;
    asm("cvt.rn.f16x2.f32 %0, %1, %2;" : "=r"(d) : "f"(k_odd), "f"(k_even));
    return d;
}

// m16n8k16 f16 mma, fp32 accumulate (sm_80 PTX, valid on base sm_103)
static __device__ __forceinline__ void mma16(float* c,
    uint32_t a0, uint32_t a1, uint32_t a2, uint32_t a3,
    uint32_t b0, uint32_t b1)
{
    asm("mma.sync.aligned.m16n8k16.row.col.f32.f16.f16.f32 "
        "{%0,%1,%2,%3}, {%4,%5,%6,%7}, {%8,%9}, {%0,%1,%2,%3};"
        : "+f"(c[0]), "+f"(c[1]), "+f"(c[2]), "+f"(c[3])
        : "r"(a0), "r"(a1), "r"(a2), "r"(a3), "r"(b0), "r"(b1));
}

// Block-wide sum over first 49 lanes' values (all 128 threads call).
static __device__ __forceinline__ float reduce49(float v, int t, float* sarr) {
    if (t < 64) sarr[t] = (t < NDIM) ? v : 0.0f;
    __syncthreads();
    if (t < 32) {
        float r = sarr[t] + sarr[t + 32];
        r += __shfl_xor_sync(0xffffffffu, r, 16);
        r += __shfl_xor_sync(0xffffffffu, r, 8);
        r += __shfl_xor_sync(0xffffffffu, r, 4);
        r += __shfl_xor_sync(0xffffffffu, r, 2);
        r += __shfl_xor_sync(0xffffffffu, r, 1);
        if (t == 0) sarr[0] = r;
    }
    __syncthreads();
    float out = sarr[0];
    __syncthreads();
    return out;
}

// load + pack one 64-channel chunk: word w (=r*49+n) <- pack(x[2r+1][n], x[2r][n])
static __device__ __forceinline__ void load_pack(const float* __restrict__ src,
                                                 uint32_t* pre, int t) {
#pragma unroll
    for (int i = 0; i < 12; i++) {
        const int w = t + i * THREADS;
        const int r = w / NDIM;
        const int n = w - r * NDIM;
        const float* p = src + (2 * r) * NDIM + n;
        pre[i] = pack_h2(__ldg(p + NDIM), __ldg(p));
    }
    if (t < 32) {                       // tail words 1536..1567
        const int w = 1536 + t;
        const int r = w / NDIM;
        const int n = w - r * NDIM;
        const float* p = src + (2 * r) * NDIM + n;
        pre[12] = pack_h2(__ldg(p + NDIM), __ldg(p));
    }
}

static __device__ __forceinline__ void store_pack(uint32_t* dst,
                                                  const uint32_t* pre, int t) {
#pragma unroll
    for (int i = 0; i < 12; i++) {
        const int w = t + i * THREADS;
        const int r = w / NDIM;
        const int n = w - r * NDIM;
        dst[r * SROW + n] = pre[i];
    }
    if (t < 32) {
        const int w = 1536 + t;
        const int r = w / NDIM;
        const int n = w - r * NDIM;
        dst[r * SROW + n] = pre[12];
    }
}

__global__ void __launch_bounds__(THREADS, 6)
ofp_fused(const float* __restrict__ x, const float* __restrict__ x0,
          float* __restrict__ out)
{
    __shared__ uint32_t sbuf[2 * BUFW];      // 18432 B
    __shared__ float sA[NDIM * NDIM];        // Gram (also finalize staging)
    __shared__ float sx[64];
    __shared__ float sred[64];
    __shared__ int scomm;

    const int t    = threadIdx.x;
    const int lane = t & 31, wid = t >> 5;
    const int l4   = lane & 3, ld4 = lane >> 2;
    const int cta  = blockIdx.x;
    const int b    = cta >> 2, q = cta & 3;
    const int qm   = wid >> 1, qn = wid & 1; // warp's 32x32 quadrant
    const int m0   = qm * 32 + ld4;
    const int n0   = qn * 32 + ld4;

    const float* __restrict__ xq =
        x + (size_t)b * (2048 * NDIM) + (size_t)q * (KQ * NDIM);

    // zero pad words n in [49,64) of both buffers (frags read n <= 63)
    for (int i = t; i < 2 * PAIRS * 15; i += THREADS) {
        const int bi  = i / (PAIRS * 15);
        const int rem = i - bi * (PAIRS * 15);
        const int r   = rem / 15;
        const int n   = NDIM + rem - r * 15;
        sbuf[bi * BUFW + r * SROW + n] = 0u;
    }

    float acc[2][4][4];
#pragma unroll
    for (int mt = 0; mt < 2; mt++)
#pragma unroll
        for (int nt = 0; nt < 4; nt++)
#pragma unroll
            for (int ci = 0; ci < 4; ci++) acc[mt][nt][ci] = 0.0f;

    // ---- prologue: chunk 0 ----
    uint32_t pre[13];
    load_pack(xq, pre, t);
    store_pack(sbuf, pre, t);
    __syncthreads();

    // ---- main loop: 8 chunks, double-buffered, 1 sync/iter ----
    for (int ch = 0; ch < NCH; ch++) {
        if (ch + 1 < NCH)
            load_pack(xq + (size_t)(ch + 1) * (KCH * NDIM), pre, t);

        const uint32_t* bc = sbuf + (ch & 1) * BUFW;
#pragma unroll
        for (int kb = 0; kb < 4; kb++) {          // 4 k16 steps (8 pairs each)
            const uint32_t* lo = bc + (kb * 8 + l4) * SROW;
            const uint32_t* hi = lo + 4 * SROW;
            uint32_t b0[4], b1[4];
#pragma unroll
            for (int nt = 0; nt < 4; nt++) {
                b0[nt] = lo[n0 + nt * 8];
                b1[nt] = hi[n0 + nt * 8];
            }
#pragma unroll
            for (int mt = 0; mt < 2; mt++) {
                const uint32_t a0 = lo[m0 + mt * 16];
                const uint32_t a1 = lo[m0 + mt * 16 + 8];
                const uint32_t a2 = hi[m0 + mt * 16];
                const uint32_t a3 = hi[m0 + mt * 16 + 8];
#pragma unroll
                for (int nt = 0; nt < 4; nt++)
                    mma16(acc[mt][nt], a0, a1, a2, a3, b0[nt], b1[nt]);
            }
        }
        if (ch + 1 < NCH)
            store_pack((uint32_t*)sbuf + ((ch + 1) & 1) * BUFW, pre, t);
        __syncthreads();
    }

    // ---- write 49x49 partial Gram ----
    {
        float* __restrict__ gp = g_partial[cta];
#pragma unroll
        for (int mt = 0; mt < 2; mt++)
#pragma unroll
            for (int nt = 0; nt < 4; nt++) {
                const int r0 = qm * 32 + mt * 16 + ld4;
                const int c0 = qn * 32 + nt * 8 + 2 * l4;
                const float* a = acc[mt][nt];
                if (r0 < NDIM) {
                    if (c0 < NDIM)     gp[r0 * NDIM + c0]     = a[0];
                    if (c0 + 1 < NDIM) gp[r0 * NDIM + c0 + 1] = a[1];
                }
                if (r0 + 8 < NDIM) {
                    if (c0 < NDIM)     gp[(r0 + 8) * NDIM + c0]     = a[2];
                    if (c0 + 1 < NDIM) gp[(r0 + 8) * NDIM + c0 + 1] = a[3];
                }
            }
    }
    __syncthreads();
    __threadfence();
    if (t == 0) scomm = atomicAdd(&g_cnt[b], 1);
    __syncthreads();
    if (scomm != NQ - 1) return;              // not the last partial of this batch

    // ================= last arriver: power iteration for batch b =================
    __threadfence();
    {
        const float* __restrict__ p0 = g_partial[(b << 2) + 0];
        const float* __restrict__ p1 = g_partial[(b << 2) + 1];
        const float* __restrict__ p2 = g_partial[(b << 2) + 2];
        const float* __restrict__ p3 = g_partial[(b << 2) + 3];
        for (int i = t; i < NDIM * NDIM; i += THREADS)
            sA[i] = (__ldcg(p0 + i) + __ldcg(p1 + i)) +
                    (__ldcg(p2 + i) + __ldcg(p3 + i));
    }
    if (t < NDIM) sx[t] = x0[b * NDIM + t];
    __syncthreads();

    // PI-1: largest eigenvalue of ATA
    for (int it = 0; it < 9; it++) {
        float y = 0.0f;
        if (t < NDIM) {
            const float* __restrict__ rA = &sA[t * NDIM];
#pragma unroll
            for (int m = 0; m < NDIM; m++) y = fmaf(rA[m], sx[m], y);
        }
        const float n2  = reduce49(y * y, t, sred);
        const float nrm = fmaxf(sqrtf(n2), EPSV);
        if (t < NDIM) sx[t] = y / nrm;
        __syncthreads();
    }
    float y = 0.0f, xv = 0.0f;
    if (t < NDIM) {
        xv = sx[t];
        const float* __restrict__ rA = &sA[t * NDIM];
#pragma unroll
        for (int m = 0; m < NDIM; m++) y = fmaf(rA[m], sx[m], y);
    }
    float num = reduce49(y * xv, t, sred);
    float den = reduce49(xv * xv, t, sred);
    const float largest = num / den;

    // PI-2 on (ATA - largest*I), warm-started from x1
    for (int it = 0; it < 9; it++) {
        float ys = 0.0f;
        if (t < NDIM) {
            const float* __restrict__ rA = &sA[t * NDIM];
#pragma unroll
            for (int m = 0; m < NDIM; m++) ys = fmaf(rA[m], sx[m], ys);
            ys -= largest * sx[t];
        }
        const float n2  = reduce49(ys * ys, t, sred);
        const float nrm = fmaxf(sqrtf(n2), EPSV);
        if (t < NDIM) sx[t] = ys / nrm;
        __syncthreads();
    }
    y = 0.0f; xv = 0.0f;
    if (t < NDIM) {
        xv = sx[t];
        const float* __restrict__ rA = &sA[t * NDIM];
#pragma unroll
        for (int m = 0; m < NDIM; m++) y = fmaf(rA[m], sx[m], y);
        y -= largest * xv;
    }
    num = reduce49(y * xv, t, sred);
    den = reduce49(xv * xv, t, sred);
    const float smallest = (num / den) + largest;

    if (t == 0) {
        const float r = largest / smallest - 1.0f;
        g_penalty[b] = r * r;                 // BETA = 1
    }
    __threadfence();
    if (t == 0) scomm = atomicAdd(&g_cnt_all, 1);
    __syncthreads();
    if (scomm != BATCH - 1) return;           // not the global last batch

    // ================= global last arriver: deterministic finalize =================
    __threadfence();
    sA[t] = __ldcg(&g_penalty[t]) + __ldcg(&g_penalty[t + 128]);
    __syncthreads();
#pragma unroll
    for (int off = 64; off > 0; off >>= 1) {
        if (t < off) sA[t] += sA[t + off];
        __syncthreads();
    }
    if (t == 0) out[0] = sA[0] * (1.0f / (float)BATCH);

    // reset counters for the next graph replay
    g_cnt[t] = 0;
    g_cnt[t + 128] = 0;
    if (t == 0) g_cnt_all = 0;
}

extern "C" void kernel_launch(void* const* d_in, const int* in_sizes, int n_in,
                              void* d_out, int out_size) {
    const float* x  = (const float*)d_in[0];   // [256, 2048, 7, 7]
    const float* x0 = (const float*)d_in[1];   // [256, 49, 1]
    float* out = (float*)d_out;

    ofp_fused<<<NCTA, THREADS>>>(x, x0, out);
}